// round 6
// baseline (speedup 1.0000x reference)
#include <cuda_runtime.h>
#include <type_traits>

namespace {

constexpr int LD  = 9;    // 2*lambd+1
constexpr int NP  = 61;   // valid (mu,m1) / (mup,m1p) pairs
constexpr int BLK = 64;   // samples (threads) per block

__host__ __device__ constexpr int imax(int a, int b) { return a > b ? a : b; }
__host__ __device__ constexpr int imin(int a, int b) { return a < b ? a : b; }

// valid m1 range for a given m2 (mu = m1+m2-4 in [0,8]); same for m1p given m2p
__host__ __device__ constexpr int lo_m(int m2) { return imax(0, 4 - m2); }
__host__ __device__ constexpr int hi_m(int m2) { return imin(8, 12 - m2); }

__host__ __device__ constexpr int cntmu(int mu) { return 9 - (mu >= 4 ? mu - 4 : 4 - mu); }
__host__ __device__ constexpr int ofsmu(int mu) {
    int o = 0;
    for (int i = 0; i < mu; i++) o += cntmu(i);
    return o;
}

// pair index p for (m1,m2): mu-major, m1 ascending (matches reference enumeration)
__host__ __device__ constexpr int pidx(int m1, int m2) {
    int mu   = m1 + m2 - 4;
    int m1lo = imax(0, mu - 4);
    return ofsmu(mu) + (m1 - m1lo);
}

// register-array layout for the per-row g[] factor (q pairs with m2p in [LO,HI))
__host__ __device__ constexpr int gcnt(int lo, int hi) {
    int c = 0;
    for (int j = lo; j < hi; j++) c += hi_m(j) - lo_m(j) + 1;
    return c;
}
__host__ __device__ constexpr int gpos(int LO, int m2p, int m1p) {
    return gcnt(LO, m2p) + (m1p - lo_m(m2p));
}

// compile-time loop: guarantees constant-folded indices (register arrays, no local mem)
template <int S, int E, class F>
__device__ __forceinline__ void static_for(F&& f) {
    if constexpr (S < E) {
        f(std::integral_constant<int, S>{});
        static_for<S + 1, E>(f);
    }
}

// One (m2, q-half) pass: builds g[] for q with m2p in [LO,HI), then accumulates
// all valid (m1, q) FFMAs for this X2 row. Everything register-resident.
template <int M2, int LO, int HI>
__device__ __forceinline__ void half_pass(const float* __restrict__ x1t,
                                          const float (&x2r)[LD],
                                          const float* __restrict__ us,
                                          const float* __restrict__ vs,
                                          float (&acc)[81]) {
    constexpr int GN = gcnt(LO, HI);
    float g[GN];
    static_for<LO, HI>([&](auto Jc) {
        constexpr int m2p = decltype(Jc)::value;
        static_for<lo_m(m2p), hi_m(m2p) + 1>([&](auto Ic) {
            constexpr int m1p = decltype(Ic)::value;
            g[gpos(LO, m2p, m1p)] = vs[pidx(m1p, m2p)] * x2r[m2p];
        });
    });
    static_for<lo_m(M2), hi_m(M2) + 1>([&](auto Mc) {
        constexpr int m1 = decltype(Mc)::value;
        const float uu = us[pidx(m1, M2)];
        float t[LD];
        static_for<0, LD>([&](auto Kc) {
            constexpr int m1p = decltype(Kc)::value;
            t[m1p] = uu * x1t[m1 * LD + m1p];   // LDS, conflict-free (stride 81 floats, odd)
        });
        static_for<LO, HI>([&](auto Jc) {
            constexpr int m2p = decltype(Jc)::value;
            static_for<lo_m(m2p), hi_m(m2p) + 1>([&](auto Ic) {
                constexpr int m1p = decltype(Ic)::value;
                acc[(m1 + M2 - 4) * LD + (m1p + m2p - 4)] += t[m1p] * g[gpos(LO, m2p, m1p)];
            });
        });
    });
}

__global__ void __launch_bounds__(BLK, 5)
wigner_kernel(const float* __restrict__ X1,
              const float* __restrict__ X2,
              const float* __restrict__ mult,
              float* __restrict__ out, int n) {
    __shared__ float x1s[BLK * 81];
    __shared__ float x2s[BLK * 81];
    __shared__ float us[NP];
    __shared__ float vs[NP];

    const int tid    = threadIdx.x;
    const int bstart = blockIdx.x * BLK;

    // Recover the rank-1 factorization of the mult table:
    //   mult[p*61+q] = c1[p]*c2[q]  ->  v[q]=mult[q], u[p]=mult[61p]/mult[0]
    if (tid < NP) {
        vs[tid] = mult[tid];
        us[tid] = mult[tid * NP] * (1.0f / mult[0]);
    }

    // Stage BOTH tiles with coalesced float4 loads. Per-sample stride of 81
    // floats (odd) makes all compute-time scalar LDS bank-conflict-free.
    // (Direct per-thread LDG of X2 costs ~32 L1 wavefronts per instruction —
    // that was the R5 bottleneck.)
    {
        const int     gbase4 = bstart * 81 / 4;  // bstart*81 % 4 == 0 since BLK=64
        const int     tot4   = n * 81 / 4;
        const float4* s1     = reinterpret_cast<const float4*>(X1);
        const float4* s2     = reinterpret_cast<const float4*>(X2);
        float4*       d1     = reinterpret_cast<float4*>(x1s);
        float4*       d2     = reinterpret_cast<float4*>(x2s);
#pragma unroll 1
        for (int k = tid; k < BLK * 81 / 4; k += BLK) {
            if (gbase4 + k < tot4) {
                d1[k] = s1[gbase4 + k];
                d2[k] = s2[gbase4 + k];
            }
        }
    }
    __syncthreads();

    float acc[81];
#pragma unroll
    for (int i = 0; i < 81; i++) acc[i] = 0.0f;

    const int s = bstart + tid;
    if (s < n) {
        const float* __restrict__ x1t = x1s + tid * 81;
        const float* __restrict__ x2t = x2s + tid * 81;
        static_for<0, LD>([&](auto M2c) {
            constexpr int m2 = decltype(M2c)::value;
            float x2r[LD];
            static_for<0, LD>([&](auto Jc) {
                constexpr int j = decltype(Jc)::value;
                x2r[j] = x2t[m2 * LD + j];       // conflict-free LDS
            });
            half_pass<m2, 0, 5>(x1t, x2r, us, vs, acc);  // g-halves cap live registers
            half_pass<m2, 5, 9>(x1t, x2r, us, vs, acc);
        });
    }

    // Bounce the result through smem (own region only -> no pre-sync hazard)
    // so the global store is fully coalesced float4s.
    if (s < n) {
#pragma unroll
        for (int i = 0; i < 81; i++) x1s[tid * 81 + i] = acc[i];
    }
    __syncthreads();
    {
        const float4* srcs   = reinterpret_cast<const float4*>(x1s);
        float4*       dsto   = reinterpret_cast<float4*>(out);
        const int     gbase4 = bstart * 81 / 4;
        const int     tot4   = n * 81 / 4;
#pragma unroll 1
        for (int k = tid; k < BLK * 81 / 4; k += BLK)
            if (gbase4 + k < tot4) dsto[gbase4 + k] = srcs[k];
    }
}

}  // namespace

extern "C" void kernel_launch(void* const* d_in, const int* in_sizes, int n_in,
                              void* d_out, int out_size) {
    const float* X1   = (const float*)d_in[0];
    const float* X2   = (const float*)d_in[1];
    const float* mult = (const float*)d_in[6];
    float*       out  = (float*)d_out;

    const int n      = in_sizes[0] / 81;
    const int blocks = (n + BLK - 1) / BLK;
    wigner_kernel<<<blocks, BLK>>>(X1, X2, mult, out, n);
}

// round 8
// speedup vs baseline: 1.3197x; 1.3197x over previous
#include <cuda_runtime.h>
#include <cstdint>
#include <type_traits>

namespace {

constexpr int LD  = 9;    // 2*lambd+1
constexpr int NP  = 61;   // valid (mu,m1) / (mup,m1p) pairs
constexpr int BLK = 64;   // samples (threads) per block
constexpr int T4  = BLK * 81 / 4;  // 1296 float4 per tile

__host__ __device__ constexpr int imax(int a, int b) { return a > b ? a : b; }
__host__ __device__ constexpr int imin(int a, int b) { return a < b ? a : b; }

__host__ __device__ constexpr int lo_m(int m2) { return imax(0, 4 - m2); }
__host__ __device__ constexpr int hi_m(int m2) { return imin(8, 12 - m2); }

__host__ __device__ constexpr int cntmu(int mu) { return 9 - (mu >= 4 ? mu - 4 : 4 - mu); }
__host__ __device__ constexpr int ofsmu(int mu) {
    int o = 0;
    for (int i = 0; i < mu; i++) o += cntmu(i);
    return o;
}

// pair index p for (m1,m2): mu-major, m1 ascending (matches reference enumeration)
__host__ __device__ constexpr int pidx(int m1, int m2) {
    int mu   = m1 + m2 - 4;
    int m1lo = imax(0, mu - 4);
    return ofsmu(mu) + (m1 - m1lo);
}

__host__ __device__ constexpr int gcnt(int lo, int hi) {
    int c = 0;
    for (int j = lo; j < hi; j++) c += hi_m(j) - lo_m(j) + 1;
    return c;
}
__host__ __device__ constexpr int gpos(int LO, int m2p, int m1p) {
    return gcnt(LO, m2p) + (m1p - lo_m(m2p));
}

template <int S, int E, class F>
__device__ __forceinline__ void static_for(F&& f) {
    if constexpr (S < E) {
        f(std::integral_constant<int, S>{});
        static_for<S + 1, E>(f);
    }
}

__device__ __forceinline__ uint32_t smem_u32(const void* p) {
    uint32_t a;
    asm("{ .reg .u64 t; cvta.to.shared.u64 t, %1; cvt.u32.u64 %0, t; }" : "=r"(a) : "l"(p));
    return a;
}

// 16B async copy, src_size 0 -> zero-fill (tail handling without branches)
__device__ __forceinline__ void cp16(uint32_t dst, const float4* src, int sz) {
    asm volatile("cp.async.cg.shared.global [%0], [%1], 16, %2;\n"
                 :: "r"(dst), "l"(src), "r"(sz));
}

// One (m2, q-half) pass: builds g[] for q with m2p in [LO,HI), then accumulates
// all valid (m1, q) FFMAs for this X2 row. Everything register-resident.
template <int M2, int LO, int HI>
__device__ __forceinline__ void half_pass(const float* __restrict__ x1t,
                                          const float (&x2r)[LD],
                                          const float* __restrict__ us,
                                          const float* __restrict__ vs,
                                          float (&acc)[81]) {
    constexpr int GN = gcnt(LO, HI);
    float g[GN];
    static_for<LO, HI>([&](auto Jc) {
        constexpr int m2p = decltype(Jc)::value;
        static_for<lo_m(m2p), hi_m(m2p) + 1>([&](auto Ic) {
            constexpr int m1p = decltype(Ic)::value;
            g[gpos(LO, m2p, m1p)] = vs[pidx(m1p, m2p)] * x2r[m2p];
        });
    });
    static_for<lo_m(M2), hi_m(M2) + 1>([&](auto Mc) {
        constexpr int m1 = decltype(Mc)::value;
        const float uu = us[pidx(m1, M2)];
        float t[LD];
        static_for<0, LD>([&](auto Kc) {
            constexpr int m1p = decltype(Kc)::value;
            t[m1p] = uu * x1t[m1 * LD + m1p];   // LDS, conflict-free (stride 81, odd)
        });
        static_for<LO, HI>([&](auto Jc) {
            constexpr int m2p = decltype(Jc)::value;
            static_for<lo_m(m2p), hi_m(m2p) + 1>([&](auto Ic) {
                constexpr int m1p = decltype(Ic)::value;
                acc[(m1 + M2 - 4) * LD + (m1p + m2p - 4)] += t[m1p] * g[gpos(LO, m2p, m1p)];
            });
        });
    });
}

__global__ void __launch_bounds__(BLK, 5)
wigner_kernel(const float* __restrict__ X1,
              const float* __restrict__ X2,
              const float* __restrict__ mult,
              float* __restrict__ out, int n) {
    __shared__ __align__(16) float x1s[BLK * 81];
    __shared__ __align__(16) float x2s[BLK * 81];
    __shared__ float us[NP];
    __shared__ float vs[NP];

    const int tid    = threadIdx.x;
    const int bstart = blockIdx.x * BLK;

    // Rank-1 refactorization of mult: mult[p*61+q] = c[p]*c[q]
    //   v[q] = mult[q], u[p] = mult[61p]/mult[0]
    if (tid < NP) {
        vs[tid] = mult[tid];
        us[tid] = mult[tid * NP] * (1.0f / mult[0]);
    }

    // Stage BOTH tiles via cp.async: 42 independent 16B copies per thread,
    // no register pressure, single wait at the end. (R6's unroll-1 LDG->STS
    // chain serialized ~600-cycle latencies and dominated the runtime.)
    {
        const int     gbase4 = bstart * 81 / 4;        // bstart*81 % 4 == 0 (BLK=64)
        const int     tot4   = n * 81 / 4;
        const float4* s1     = reinterpret_cast<const float4*>(X1);
        const float4* s2     = reinterpret_cast<const float4*>(X2);
        const uint32_t d1    = smem_u32(x1s);
        const uint32_t d2    = smem_u32(x2s);
#pragma unroll
        for (int k = 0; k < (T4 + BLK - 1) / BLK; k++) {   // 21 slots
            const int idx = k * BLK + tid;
            if (idx < T4) {
                const int sz = (gbase4 + idx < tot4) ? 16 : 0;  // tail -> zero-fill
                cp16(d1 + idx * 16, s1 + gbase4 + idx, sz);
                cp16(d2 + idx * 16, s2 + gbase4 + idx, sz);
            }
        }
        asm volatile("cp.async.commit_group;\n");
        asm volatile("cp.async.wait_group 0;\n" ::: "memory");
    }
    __syncthreads();

    float acc[81];
#pragma unroll
    for (int i = 0; i < 81; i++) acc[i] = 0.0f;

    {
        const float* __restrict__ x1t = x1s + tid * 81;
        const float* __restrict__ x2t = x2s + tid * 81;
        static_for<0, LD>([&](auto M2c) {
            constexpr int m2 = decltype(M2c)::value;
            float x2r[LD];
            static_for<0, LD>([&](auto Jc) {
                constexpr int j = decltype(Jc)::value;
                x2r[j] = x2t[m2 * LD + j];        // conflict-free LDS
            });
            half_pass<m2, 0, 5>(x1t, x2r, us, vs, acc);   // g-halves cap live regs
            half_pass<m2, 5, 9>(x1t, x2r, us, vs, acc);
        });
    }

    // Stage result in smem (x1 tile is dead) for fully coalesced float4 stores.
#pragma unroll
    for (int i = 0; i < 81; i++) x1s[tid * 81 + i] = acc[i];
    __syncthreads();
    {
        const float4* srcs   = reinterpret_cast<const float4*>(x1s);
        float4*       dsto   = reinterpret_cast<float4*>(out);
        const int     gbase4 = bstart * 81 / 4;
        const int     tot4   = n * 81 / 4;
#pragma unroll
        for (int k = 0; k < (T4 + BLK - 1) / BLK; k++) {
            const int idx = k * BLK + tid;
            if (idx < T4 && gbase4 + idx < tot4) dsto[gbase4 + idx] = srcs[idx];
        }
    }
}

}  // namespace

extern "C" void kernel_launch(void* const* d_in, const int* in_sizes, int n_in,
                              void* d_out, int out_size) {
    const float* X1   = (const float*)d_in[0];
    const float* X2   = (const float*)d_in[1];
    const float* mult = (const float*)d_in[6];
    float*       out  = (float*)d_out;

    const int n      = in_sizes[0] / 81;
    const int blocks = (n + BLK - 1) / BLK;
    wigner_kernel<<<blocks, BLK>>>(X1, X2, mult, out, n);
}